// round 10
// baseline (speedup 1.0000x reference)
#include <cuda_runtime.h>
#include <cstdint>

// Problem dims (fixed by the reference setup)
#define BATCH   8
#define NT      1024          // N*T
#define MLANES  64            // M
#define LPTS    16            // L
#define NEMBD   128
#define EDIM    12
#define NPOS    (BATCH * NT * MLANES)   // 524288

#define ROWS_PB 8             // agent rows per block
#define POS_PB  (ROWS_PB * MLANES)      // 512 positions per block
#define TPB     256
#define NWARP   8
#define CHUNK   (POS_PB / NWARP)        // 64 positions per warp
#define BATCH_POS 8                     // positions per bulk store (4 KB)
#define NBATCH  (CHUNK / BATCH_POS)     // 8 batches per warp

// Dynamic smem layout (bytes)
#define SM_LANE   0                               // float4[1024]  = 16384
#define SM_EDGE   16384                           // float[512*12] = 24576
#define SM_AGENT  (16384 + 24576)                 // float[64]     = 256
#define SM_STAGE  (16384 + 24576 + 256)           // 8 warps * 2 bufs * 4096 B
#define SMEM_TOTAL (SM_STAGE + NWARP * 2 * 4096)  // 106752

typedef unsigned long long u64;

// ---------------------------------------------------------------------------
// packed f32x2 helpers (Blackwell)
// ---------------------------------------------------------------------------
__device__ __forceinline__ u64 pack2(float a, float b) {
    u64 r;
    asm("mov.b64 %0, {%1,%2};" : "=l"(r) : "f"(a), "f"(b));
    return r;
}
__device__ __forceinline__ void unpack2(u64 v, float& a, float& b) {
    asm("mov.b64 {%0,%1}, %2;" : "=f"(a), "=f"(b) : "l"(v));
}
__device__ __forceinline__ void fma2(u64& acc, u64 a, u64 b) {
    asm("fma.rn.f32x2 %0, %1, %2, %0;" : "+l"(acc) : "l"(a), "l"(b));
}

__device__ __forceinline__ float4 dx_at(float px, float py, float ps, float pc,
                                        float flag1, float4 q) {
    float f2 = (q.x == 0.f && q.y == 0.f && q.z == 0.f && q.w == 0.f) ? 0.f : 1.f;
    float f  = flag1 * f2;
    float dxw = px - q.x;
    float dyw = py - q.y;
    float dX = (dxw * q.w + dyw * q.z) * 0.1f * f;   // delta_x / 10
    float dY = (-dxw * q.z + dyw * q.w) * 0.1f * f;  // delta_y / 10
    float ds = (ps * q.w - pc * q.z) * f;
    float dc = (pc * q.w + ps * q.z) * f;
    return make_float4(dX, dY, ds, dc);
}

// ---------------------------------------------------------------------------
// Fused kernel. Phase B identical compute to the R7 design (one warp per
// position, 4 channels/lane, f32x2 FMAs); epilogue rewritten: results staged
// in smem and drained via cp.async.bulk (TMA bulk engine) instead of STG.
// ---------------------------------------------------------------------------
__global__ void __launch_bounds__(TPB, 2)
fused_kernel(const float* __restrict__ agent,
             const float* __restrict__ lane,
             const float* __restrict__ W,
             const float* __restrict__ bias,
             float* __restrict__ out) {
    extern __shared__ __align__(16) char smem[];
    float4* slane  = reinterpret_cast<float4*>(smem + SM_LANE);   // [l][m]
    float*  sedge  = reinterpret_cast<float*>(smem + SM_EDGE);
    float*  sagent = reinterpret_cast<float*>(smem + SM_AGENT);

    const int tid  = threadIdx.x;
    const size_t row0 = (size_t)blockIdx.x * ROWS_PB;        // global agent row base
    const int b = (int)(row0 >> 10);

    // ---- Phase 0: stage lane (transposed [l][m]) + agent rows ----
    const float4* lg = reinterpret_cast<const float4*>(lane) + (size_t)b * MLANES * LPTS;
#pragma unroll
    for (int k = 0; k < 4; k++) {
        int s = tid + k * 256;            // s = l*64 + m
        int l = s >> 6, m = s & 63;
        slane[s] = __ldg(lg + m * LPTS + l);
    }
    if (tid < ROWS_PB * 8)
        sagent[tid] = __ldg(agent + row0 * 8 + tid);

    // ---- Per-lane weights for 4 channels ----
    const int warp = tid >> 5;
    const int lid  = tid & 31;
    const int e0   = lid * 4;             // this lane's first channel

    u64 wp[4][6];
#pragma unroll
    for (int c = 0; c < 4; c++) {
        const float* wrow = W + (e0 + c) * EDIM;
#pragma unroll
        for (int k = 0; k < 6; k++)
            wp[c][k] = pack2(__ldg(wrow + 2 * k), __ldg(wrow + 2 * k + 1));
    }
    u64 binit[4];
#pragma unroll
    for (int c = 0; c < 4; c++)
        binit[c] = pack2(__ldg(bias + e0 + c), 0.f);

    __syncthreads();

    // ---- Phase A: edge features into smem (2 positions per thread) ----
#pragma unroll
    for (int it = 0; it < 2; it++) {
        int p = tid + it * 256;           // local position
        int r = p >> 6, m = p & 63;
        const float* ar = sagent + r * 8;
        float a0 = ar[0], a1 = ar[1], a2 = ar[2], a3 = ar[3];
        float a4 = ar[4], a5 = ar[5], a6 = ar[6], a7 = ar[7];
        float flag1 = (a0 == 0.f && a1 == 0.f && a2 == 0.f && a3 == 0.f &&
                       a4 == 0.f && a5 == 0.f && a6 == 0.f && a7 == 0.f) ? 0.f : 1.f;
        float px = a0, py = a1, ps = a3, pc = a4;

        float bestAbs = 3.4e38f;
        int   bestl   = 0;
#pragma unroll
        for (int l = 0; l < LPTS; l++) {
            float4 q = slane[l * MLANES + m];     // contiguous LDS.128, conflict-free
            float f2 = (q.x == 0.f && q.y == 0.f && q.z == 0.f && q.w == 0.f) ? 0.f : 1.f;
            float f01 = 0.1f * flag1 * f2;
            float dxw = px - q.x;
            float dyw = py - q.y;
            float aX = fabsf((dxw * q.w + dyw * q.z) * f01);
            if (aX < bestAbs) { bestAbs = aX; bestl = l; }   // strict < = first-min
        }

        float4 mp  = dx_at(px, py, ps, pc, flag1, slane[bestl * MLANES + m]);
        float4 el0 = dx_at(px, py, ps, pc, flag1, slane[0 * MLANES + m]);
        float4 elL = dx_at(px, py, ps, pc, flag1, slane[(LPTS - 1) * MLANES + m]);

        float4* ep = reinterpret_cast<float4*>(sedge + p * EDIM);   // rows 16B-aligned
        ep[0] = mp;
        ep[1] = el0;
        ep[2] = elL;
    }

    __syncthreads();

    // ---- Phase B: one warp per position; TMA bulk-store epilogue ----
    const int chunk0 = warp * CHUNK;                         // local position base
    const ulonglong2* eptr =
        reinterpret_cast<const ulonglong2*>(sedge + chunk0 * EDIM);
    float* gdst0 = out + ((size_t)blockIdx.x * POS_PB + chunk0) * NEMBD;

    char* stage0 = smem + SM_STAGE + warp * 2 * 4096;        // two 4 KB buffers

#pragma unroll 1
    for (int bt = 0; bt < NBATCH; bt++) {
        float* sb = reinterpret_cast<float*>(stage0 + (bt & 1) * 4096);

#pragma unroll
        for (int it = 0; it < BATCH_POS / 2; it++) {
            // Both positions' edge rows up front: 6 independent LDS.128 (broadcast)
            ulonglong2 qa0 = eptr[0], qa1 = eptr[1], qa2 = eptr[2];   // position A
            ulonglong2 qb0 = eptr[3], qb1 = eptr[4], qb2 = eptr[5];   // position B
            eptr += 6;

            u64 evA[6] = { qa0.x, qa0.y, qa1.x, qa1.y, qa2.x, qa2.y };
            u64 evB[6] = { qb0.x, qb0.y, qb1.x, qb1.y, qb2.x, qb2.y };

            u64 aA[4], aB[4];
#pragma unroll
            for (int c = 0; c < 4; c++) { aA[c] = binit[c]; aB[c] = binit[c]; }

#pragma unroll
            for (int k = 0; k < 6; k++) {
#pragma unroll
                for (int c = 0; c < 4; c++) {
                    fma2(aA[c], evA[k], wp[c][k]);
                    fma2(aB[c], evB[k], wp[c][k]);
                }
            }

            float4 oA, oB;
            {
                float lo, hi;
                unpack2(aA[0], lo, hi); oA.x = lo + hi;
                unpack2(aA[1], lo, hi); oA.y = lo + hi;
                unpack2(aA[2], lo, hi); oA.z = lo + hi;
                unpack2(aA[3], lo, hi); oA.w = lo + hi;
                unpack2(aB[0], lo, hi); oB.x = lo + hi;
                unpack2(aB[1], lo, hi); oB.y = lo + hi;
                unpack2(aB[2], lo, hi); oB.z = lo + hi;
                unpack2(aB[3], lo, hi); oB.w = lo + hi;
            }

            // Stage into smem: 32 lanes x 16B contiguous -> conflict-free STS.128
            reinterpret_cast<float4*>(sb + (it * 2 + 0) * NEMBD)[lid] = oA;
            reinterpret_cast<float4*>(sb + (it * 2 + 1) * NEMBD)[lid] = oB;
        }

        __syncwarp();
        if (lid == 0) {
            // Order generic STS before async-proxy bulk read
            asm volatile("fence.proxy.async.shared::cta;" ::: "memory");
            uint32_t ssrc;
            asm("{ .reg .u64 t; cvta.to.shared.u64 t, %1; cvt.u32.u64 %0, t; }"
                : "=r"(ssrc) : "l"(sb));
            const float* gdst = gdst0 + (size_t)bt * BATCH_POS * NEMBD;
            asm volatile(
                "cp.async.bulk.global.shared::cta.bulk_group [%0], [%1], %2;"
                :: "l"(gdst), "r"(ssrc), "r"((uint32_t)(BATCH_POS * NEMBD * 4))
                : "memory");
            asm volatile("cp.async.bulk.commit_group;" ::: "memory");
            // <=1 group in flight -> the buffer 2 batches old is reusable
            asm volatile("cp.async.bulk.wait_group.read 1;" ::: "memory");
        }
        __syncwarp();
    }

    // Flush all pending bulk stores before exit
    if (lid == 0)
        asm volatile("cp.async.bulk.wait_group 0;" ::: "memory");
}

// ---------------------------------------------------------------------------
// Launch: inputs in metadata order: agent, lane, W, b. Output fp32.
// ---------------------------------------------------------------------------
extern "C" void kernel_launch(void* const* d_in, const int* in_sizes, int n_in,
                              void* d_out, int out_size) {
    const float* agent = (const float*)d_in[0];
    const float* lane  = (const float*)d_in[1];
    const float* W     = (const float*)d_in[2];
    const float* bias  = (const float*)d_in[3];
    float* out = (float*)d_out;

    static int attr_done = 0;
    if (!attr_done) {
        cudaFuncSetAttribute(fused_kernel,
                             cudaFuncAttributeMaxDynamicSharedMemorySize, SMEM_TOTAL);
        attr_done = 1;
    }

    fused_kernel<<<NPOS / POS_PB, TPB, SMEM_TOTAL>>>(agent, lane, W, bias, out);
}

// round 11
// speedup vs baseline: 1.0593x; 1.0593x over previous
#include <cuda_runtime.h>
#include <cstdint>

// Problem dims (fixed by the reference setup)
#define BATCH   8
#define NT      1024          // N*T
#define MLANES  64            // M
#define LPTS    16            // L
#define NEMBD   128
#define EDIM    12
#define NPOS    (BATCH * NT * MLANES)   // 524288

#define ROWS_PB 8             // agent rows per block
#define POS_PB  (ROWS_PB * MLANES)      // 512 positions per block
#define TPB     256
#define CHUNK   (POS_PB / 4)  // 128 positions per warp-pair

typedef unsigned long long u64;

// ---------------------------------------------------------------------------
// packed f32x2 helpers (Blackwell)
// ---------------------------------------------------------------------------
__device__ __forceinline__ u64 pack2(float a, float b) {
    u64 r;
    asm("mov.b64 %0, {%1,%2};" : "=l"(r) : "f"(a), "f"(b));
    return r;
}
__device__ __forceinline__ void unpack2(u64 v, float& a, float& b) {
    asm("mov.b64 {%0,%1}, %2;" : "=f"(a), "=f"(b) : "l"(v));
}
__device__ __forceinline__ void fma2(u64& acc, u64 a, u64 b) {
    asm("fma.rn.f32x2 %0, %1, %2, %0;" : "+l"(acc) : "l"(a), "l"(b));
}

__device__ __forceinline__ float4 dx_at(float px, float py, float ps, float pc,
                                        float flag1, float4 q) {
    float f2 = (q.x == 0.f && q.y == 0.f && q.z == 0.f && q.w == 0.f) ? 0.f : 1.f;
    float f  = flag1 * f2;
    float dxw = px - q.x;
    float dyw = py - q.y;
    float dX = (dxw * q.w + dyw * q.z) * 0.1f * f;   // delta_x / 10
    float dY = (-dxw * q.z + dyw * q.w) * 0.1f * f;  // delta_y / 10
    float ds = (ps * q.w - pc * q.z) * f;
    float dc = (pc * q.w + ps * q.z) * f;
    return make_float4(dX, dY, ds, dc);
}

// ---------------------------------------------------------------------------
// Fused kernel: edge features (smem-local) + projection.
// Occupancy-focused build: launch_bounds(256,4) (64-reg budget -> 32 warps/SM).
// Phase B = R3's warp-pair scheme (lane owns 2 channels, 24 weight regs),
// no position unroll, edge rows via 3x LDS.128, pointer-bump addressing.
// Weights are loaded AFTER Phase A to keep peak register pressure low.
// ---------------------------------------------------------------------------
__global__ void __launch_bounds__(TPB, 4)
fused_kernel(const float* __restrict__ agent,
             const float* __restrict__ lane,
             const float* __restrict__ W,
             const float* __restrict__ bias,
             float* __restrict__ out) {
    __shared__ __align__(16) float4 slane[LPTS * MLANES];    // [l][m], 16 KB
    __shared__ float sagent[ROWS_PB * 8];                    // 256 B
    __shared__ __align__(16) float sedge[POS_PB * EDIM];     // 24 KB

    const int tid  = threadIdx.x;
    const size_t row0 = (size_t)blockIdx.x * ROWS_PB;        // global agent row base
    const int b = (int)(row0 >> 10);

    // ---- Phase 0: stage lane (transposed [l][m]) + agent rows ----
    const float4* lg = reinterpret_cast<const float4*>(lane) + (size_t)b * MLANES * LPTS;
#pragma unroll
    for (int k = 0; k < 4; k++) {
        int s = tid + k * 256;            // s = l*64 + m
        int l = s >> 6, m = s & 63;
        slane[s] = __ldg(lg + m * LPTS + l);
    }
    if (tid < ROWS_PB * 8)
        sagent[tid] = __ldg(agent + row0 * 8 + tid);
    __syncthreads();

    // ---- Phase A: edge features into smem (2 positions per thread) ----
#pragma unroll
    for (int it = 0; it < 2; it++) {
        int p = tid + it * 256;           // local position
        int r = p >> 6, m = p & 63;
        const float* ar = sagent + r * 8;
        float a0 = ar[0], a1 = ar[1], a2 = ar[2], a3 = ar[3];
        float a4 = ar[4], a5 = ar[5], a6 = ar[6], a7 = ar[7];
        float flag1 = (a0 == 0.f && a1 == 0.f && a2 == 0.f && a3 == 0.f &&
                       a4 == 0.f && a5 == 0.f && a6 == 0.f && a7 == 0.f) ? 0.f : 1.f;
        float px = a0, py = a1, ps = a3, pc = a4;

        float bestAbs = 3.4e38f;
        int   bestl   = 0;
#pragma unroll
        for (int l = 0; l < LPTS; l++) {
            float4 q = slane[l * MLANES + m];     // contiguous LDS.128, conflict-free
            float f2 = (q.x == 0.f && q.y == 0.f && q.z == 0.f && q.w == 0.f) ? 0.f : 1.f;
            float f01 = 0.1f * flag1 * f2;
            float dxw = px - q.x;
            float dyw = py - q.y;
            float aX = fabsf((dxw * q.w + dyw * q.z) * f01);
            if (aX < bestAbs) { bestAbs = aX; bestl = l; }   // strict < = first-min
        }

        float4 mp  = dx_at(px, py, ps, pc, flag1, slane[bestl * MLANES + m]);
        float4 el0 = dx_at(px, py, ps, pc, flag1, slane[0 * MLANES + m]);
        float4 elL = dx_at(px, py, ps, pc, flag1, slane[(LPTS - 1) * MLANES + m]);

        float4* ep = reinterpret_cast<float4*>(sedge + p * EDIM);   // rows 16B-aligned
        ep[0] = mp;
        ep[1] = el0;
        ep[2] = elL;
    }

    // ---- Load per-lane weights for 2 channels (after Phase A: low reg peak) ----
    const int warp = tid >> 5;
    const int lid  = tid & 31;
    const int e0   = (warp & 1) * 64 + lid * 2;   // this lane's first channel

    u64 wp0[6], wp1[6];
#pragma unroll
    for (int k = 0; k < 6; k++) {
        wp0[k] = pack2(__ldg(W + (e0 + 0) * EDIM + 2 * k), __ldg(W + (e0 + 0) * EDIM + 2 * k + 1));
        wp1[k] = pack2(__ldg(W + (e0 + 1) * EDIM + 2 * k), __ldg(W + (e0 + 1) * EDIM + 2 * k + 1));
    }
    const u64 b0 = pack2(__ldg(bias + e0 + 0), 0.f);
    const u64 b1 = pack2(__ldg(bias + e0 + 1), 0.f);

    __syncthreads();

    // ---- Phase B: warp-pair owns a contiguous 128-position chunk ----
    const int pair = warp >> 1;
    const ulonglong2* eptr =
        reinterpret_cast<const ulonglong2*>(sedge + pair * CHUNK * EDIM);
    float* optr = out + ((size_t)blockIdx.x * POS_PB + (size_t)pair * CHUNK) * NEMBD + e0;

#pragma unroll 1
    for (int it = 0; it < CHUNK; it++) {
        // Edge row: 3 independent LDS.128 (broadcast)
        ulonglong2 q0 = eptr[0], q1 = eptr[1], q2 = eptr[2];
        eptr += 3;

        u64 acc0 = b0, acc1 = b1;
        fma2(acc0, q0.x, wp0[0]); fma2(acc1, q0.x, wp1[0]);
        fma2(acc0, q0.y, wp0[1]); fma2(acc1, q0.y, wp1[1]);
        fma2(acc0, q1.x, wp0[2]); fma2(acc1, q1.x, wp1[2]);
        fma2(acc0, q1.y, wp0[3]); fma2(acc1, q1.y, wp1[3]);
        fma2(acc0, q2.x, wp0[4]); fma2(acc1, q2.x, wp1[4]);
        fma2(acc0, q2.y, wp0[5]); fma2(acc1, q2.y, wp1[5]);

        float l0, h0, l1, h1;
        unpack2(acc0, l0, h0);
        unpack2(acc1, l1, h1);

        __stcs(reinterpret_cast<float2*>(optr), make_float2(l0 + h0, l1 + h1));
        optr += NEMBD;
    }
}

// ---------------------------------------------------------------------------
// Launch: inputs in metadata order: agent, lane, W, b. Output fp32.
// ---------------------------------------------------------------------------
extern "C" void kernel_launch(void* const* d_in, const int* in_sizes, int n_in,
                              void* d_out, int out_size) {
    const float* agent = (const float*)d_in[0];
    const float* lane  = (const float*)d_in[1];
    const float* W     = (const float*)d_in[2];
    const float* bias  = (const float*)d_in[3];
    float* out = (float*)d_out;

    fused_kernel<<<NPOS / POS_PB, TPB>>>(agent, lane, W, bias, out);
}